// round 9
// baseline (speedup 1.0000x reference)
#include <cuda_runtime.h>

// CharRNN: B=512, T=2048, VOCAB=96, EMBED=32, HIDDEN=128
// R8: same pipe-balanced design as R7, with 2x warps in both kernels to close
// the latency-exposure gap (floors unchanged).
//  Cell: 128 CTAs x 512 thr (16 warps). Thread = (j-quad, k-16th of 8 k).
//        Per k: 2 LDS.64 + 8 FFMA2. 4-level shfl reduce (xor 8,4,2 scatter +
//        xor 1 allreduce); even lanes write. h row-pair packed + k-padded.
//  Dec : 8192 CTAs x 256 thr, 2 CTAs/SM (16 warps/SM). Thread Mr=8 rows x
//        Nr=6 v. W scalar smem (stride 97); H [k][rp] u64-packed smem.

#define VOCABN 96
#define EMBEDN 32
#define HID    128
#define BATCH  512
#define TLEN   2048
#define BROWS  4
#define NBLK   (BATCH / BROWS)   // 128
#define CTHR   512
#define WCS    (EMBEDN + HID)    // 160
#define ETS    132               // padded Et row stride (floats)

typedef unsigned long long u64;

// hidden states, row-pair packed: g_H[(t*256 + b/2)*128 + j] = (h[2rp][j], h[2rp+1][j])
__device__ u64 g_H[(size_t)TLEN * (BATCH / 2) * HID];

__device__ __forceinline__ u64 ffma2(u64 a, u64 b, u64 c) {
    u64 d;
    asm("fma.rn.f32x2 %0, %1, %2, %3;" : "=l"(d) : "l"(a), "l"(b), "l"(c));
    return d;
}
__device__ __forceinline__ u64 fadd2(u64 a, u64 b) {
    u64 d;
    asm("add.rn.f32x2 %0, %1, %2;" : "=l"(d) : "l"(a), "l"(b));
    return d;
}
__device__ __forceinline__ u64 pack2(float x, float y) {
    u64 d;
    asm("mov.b64 %0, {%1, %2};" : "=l"(d) : "f"(x), "f"(y));
    return d;
}
__device__ __forceinline__ float2 unpack2(u64 a) {
    float2 r;
    asm("mov.b64 {%0, %1}, %2;" : "=f"(r.x), "=f"(r.y) : "l"(a));
    return r;
}
__device__ __forceinline__ u64 shflx64(u64 v, int m) {
    float2 p = unpack2(v);
    p.x = __shfl_xor_sync(0xffffffffu, p.x, m);
    p.y = __shfl_xor_sync(0xffffffffu, p.y, m);
    return pack2(p.x, p.y);
}
__device__ __forceinline__ float tanh_fast(float x) {
    float e;
    asm("ex2.approx.f32 %0, %1;" : "=f"(e) : "f"(x * 2.8853900817779268f));
    float r;
    asm("rcp.approx.f32 %0, %1;" : "=f"(r) : "f"(e + 1.0f));
    return fmaf(-2.0f, r, 1.0f);
}

// ---------------- cell kernel ----------------
// smem: Et[96][132] floats, hp: 2 buf x 2 rp x 136 u64 (k -> k + (k>>4)),
//       xs: 2048*4 ints
#define HP_RP   136
#define HP_BUF  (2 * HP_RP)
#define F_ET 0
#define F_HP (F_ET + VOCABN*ETS)
#define F_XS (F_HP + 2*HP_BUF*2)
#define C_SMEM_FLOATS (F_XS + BROWS*TLEN)
#define C_SMEM_BYTES  (C_SMEM_FLOATS * 4)

__global__ void __launch_bounds__(CTHR, 1)
charrnn_cell_kernel(const int* __restrict__ x,
                    const float* __restrict__ h0,
                    const float* __restrict__ emb,
                    const float* __restrict__ Wcell,
                    const float* __restrict__ bcell,
                    float* __restrict__ hfin)
{
    extern __shared__ float smem[];
    float* Et  = smem + F_ET;
    u64*   hpU = (u64*)(smem + F_HP);
    int*   xs  = (int*)(smem + F_XS);

    const int tid = threadIdx.x;
    const int b0  = blockIdx.x * BROWS;

    const int s  = tid & 15;         // k-slice: k in [8s, 8s+8)
    const int jq = tid >> 4;         // j-quad 0..31
    const int jb = jq * 4;

    // duplicated (w,w): wd[jj][kk] for j = jb+jj, k = 8s+kk
    u64 wd[4][8];
    #pragma unroll
    for (int jj = 0; jj < 4; jj++) {
        const float* p = Wcell + (jb + jj) * WCS + EMBEDN + s * 8;
        #pragma unroll
        for (int kk = 0; kk < 8; kk++) {
            float w = p[kk];
            wd[jj][kk] = pack2(w, w);
        }
    }

    // Et table (threads 0..127)
    if (tid < HID) {
        const int j = tid;
        float we[EMBEDN];
        #pragma unroll
        for (int k = 0; k < EMBEDN; k++)
            we[k] = Wcell[j * WCS + k];
        const float bc = bcell[j];
        for (int vv = 0; vv < VOCABN; vv++) {
            float a = bc;
            #pragma unroll
            for (int k = 0; k < EMBEDN; k++)
                a = fmaf(emb[vv * EMBEDN + k], we[k], a);
            Et[vv * ETS + j] = a;
        }
    }

    // token prefetch: xs[t*4 + r] = x[(b0+r)*T + t]
    for (int i = tid; i < BROWS * TLEN; i += CTHR) {
        int t = i >> 2, r = i & 3;
        xs[i] = x[(b0 + r) * TLEN + t];
    }

    // initial h -> buffer 0 (row-pair packed, padded)
    if (tid < 256) {
        const int rp = tid >> 7;
        const int jj = tid & 127;
        u64 v = pack2(h0[(b0 + 2 * rp) * HID + jj],
                      h0[(b0 + 2 * rp + 1) * HID + jj]);
        hpU[rp * HP_RP + jj + (jj >> 4)] = v;
    }
    __syncthreads();

    // output mapping (after reduction): j = jb + 2*bit2(s) + bit1(s), rp = bit3(s)
    const int rp   = s >> 3;
    const int jfin = jb + ((s >> 1) & 2) + ((s >> 1) & 1);
    const int jfp  = jfin + (jfin >> 4);
    const bool wr  = (s & 1) == 0;
    const size_t gbase = (size_t)(b0 >> 1) + rp;
    const int slb = 8 * s + (s >> 1);       // padded slice base
    float th0 = 0.f, th1 = 0.f;

    #pragma unroll 1
    for (int t = 0; t < TLEN; t++) {
        const u64* hb  = hpU + (t & 1) * HP_BUF;
        const u64* h0p = hb + slb;           // rp 0, my k-slice
        const u64* h1p = h0p + HP_RP;        // rp 1

        u64 a0[4] = {0, 0, 0, 0};
        u64 a1[4] = {0, 0, 0, 0};
        #pragma unroll
        for (int kk = 0; kk < 8; kk++) {
            u64 hA = h0p[kk];
            u64 hB = h1p[kk];
            #pragma unroll
            for (int jj = 0; jj < 4; jj++) {
                a0[jj] = ffma2(hA, wd[jj][kk], a0[jj]);
                a1[jj] = ffma2(hB, wd[jj][kk], a1[jj]);
            }
        }

        // xor8: bit3 selects rp
        u64 kp[4];
        #pragma unroll
        for (int jj = 0; jj < 4; jj++) {
            u64 keep = (s & 8) ? a1[jj] : a0[jj];
            u64 give = (s & 8) ? a0[jj] : a1[jj];
            kp[jj] = fadd2(keep, shflx64(give, 8));
        }
        // xor4: bit2 selects jj-pair
        u64 kA = (s & 4) ? kp[2] : kp[0];
        u64 gA = (s & 4) ? kp[0] : kp[2];
        kA = fadd2(kA, shflx64(gA, 4));
        u64 kB = (s & 4) ? kp[3] : kp[1];
        u64 gB = (s & 4) ? kp[1] : kp[3];
        kB = fadd2(kB, shflx64(gB, 4));
        // xor2: bit1 selects
        u64 kk2 = (s & 2) ? kB : kA;
        u64 gg  = (s & 2) ? kA : kB;
        kk2 = fadd2(kk2, shflx64(gg, 2));
        // xor1: allreduce (both lanes get the full sum)
        kk2 = fadd2(kk2, shflx64(kk2, 1));

        // finalize rows (2rp, 2rp+1) at hidden index jfin
        const int i0 = xs[t * 4 + 2 * rp];
        const int i1 = xs[t * 4 + 2 * rp + 1];
        float2 u = unpack2(kk2);
        th0 = tanh_fast(u.x + Et[i0 * ETS + jfin]);
        th1 = tanh_fast(u.y + Et[i1 * ETS + jfin]);
        if (wr) {
            u64 hv = pack2(th0, th1);
            hpU[((t + 1) & 1) * HP_BUF + rp * HP_RP + jfp] = hv;
            g_H[((size_t)t * (BATCH / 2) + gbase) * HID + jfin] = hv;
        }
        __syncthreads();
    }

    if (hfin && wr) {
        hfin[(b0 + 2 * rp) * HID + jfin]     = th0;
        hfin[(b0 + 2 * rp + 1) * HID + jfin] = th1;
    }
}

// ---------------- decoder GEMM kernel ----------------
// out[b][t][v] = H[t][b][:] . Wdec[v][:] + bdec[v]
// CTA: 128 rows (64 rp) x 96 v, 256 thr = 16 rg x 16 vg. Thread: Mr=8 x Nr=6.
#define D_ROWS 128
#define D_THR  256
#define WS_S   97

// smem: htp u64[128][64] = 64KB; ws float[128][97] = 48.5KB; bias 96 floats
#define U_HTP  0
#define U_END  (U_HTP + 128*64)             // u64 units
#define D_WS_OFF   (U_END * 2)              // float index
#define D_BIAS_OFF (D_WS_OFF + 128*WS_S)
#define D_SMEM_FLOATS (D_BIAS_OFF + 96)
#define D_SMEM_BYTES  (D_SMEM_FLOATS * 4)

__global__ void __launch_bounds__(D_THR, 2)
charrnn_dec_kernel(const float* __restrict__ Wdec,   // [96][128]
                   const float* __restrict__ bdec,   // [96]
                   float* __restrict__ out)          // [512][2048][96]
{
    extern __shared__ u64 smemU[];
    u64*   htp  = smemU + U_HTP;                     // [k][rp]
    float* ws   = (float*)smemU + D_WS_OFF;          // [k][97]
    float* bias = (float*)smemU + D_BIAS_OFF;

    const int tid = threadIdx.x;
    const int t_idx = blockIdx.x >> 2;
    const int bb0   = (blockIdx.x & 3) * D_ROWS;
    const size_t rpg0 = (size_t)t_idx * (BATCH / 2) + (bb0 >> 1);

    // stage W scalar: ws[k*97 + v] = Wdec[v][k]   (stride 97 -> conflict-free)
    for (int i = tid; i < VOCABN * HID; i += D_THR) {
        int v = i >> 7, k = i & 127;
        ws[k * WS_S + v] = Wdec[i];
    }
    if (tid < VOCABN) bias[tid] = bdec[tid];

    // stage H: htp[k][rp] = g_H[rpg0 + rp][k]   (32 u64 per thread, LDG.128)
    {
        const int rp = tid >> 2;
        const int q  = tid & 3;                  // k-quarter
        const ulonglong2* src =
            (const ulonglong2*)(g_H + (rpg0 + rp) * HID + q * 32);
        #pragma unroll
        for (int i = 0; i < 16; i++) {
            ulonglong2 hv = src[i];
            int k = q * 32 + 2 * i;
            htp[(k + 0) * 64 + rp] = hv.x;
            htp[(k + 1) * 64 + rp] = hv.y;
        }
    }
    __syncthreads();

    const int vg = tid & 15;
    const int rg = tid >> 4;
    const int v0 = vg * 6;

    u64 acc[4][6];
    #pragma unroll
    for (int i = 0; i < 4; i++)
        #pragma unroll
        for (int q = 0; q < 6; q++)
            acc[i][q] = 0ull;

    const u64*   hB = htp + rg * 4;
    const float* wB = ws + v0;

    #pragma unroll 4
    for (int k = 0; k < HID; k++) {
        u64 h[4];
        {
            const ulonglong2* hp2 = (const ulonglong2*)(hB + k * 64);
            ulonglong2 hv0 = hp2[0];
            ulonglong2 hv1 = hp2[1];
            h[0] = hv0.x; h[1] = hv0.y; h[2] = hv1.x; h[3] = hv1.y;
        }
        #pragma unroll
        for (int q = 0; q < 6; q++) {
            float w = wB[k * WS_S + q];
            u64 w2 = pack2(w, w);
            #pragma unroll
            for (int i = 0; i < 4; i++)
                acc[i][q] = ffma2(h[i], w2, acc[i][q]);
        }
    }

    // epilogue
    float bq[6];
    #pragma unroll
    for (int q = 0; q < 6; q++)
        bq[q] = bias[v0 + q];

    #pragma unroll
    for (int i = 0; i < 4; i++) {
        const int rpl = rg * 4 + i;
        const int be  = bb0 + 2 * rpl;           // even batch row
        float* oe = out + ((size_t)be * TLEN + t_idx) * VOCABN + v0;
        float* oo = oe + (size_t)TLEN * VOCABN;
        float fe[6], fo[6];
        #pragma unroll
        for (int q = 0; q < 6; q++) {
            float2 p = unpack2(acc[i][q]);
            fe[q] = p.x + bq[q];
            fo[q] = p.y + bq[q];
        }
        #pragma unroll
        for (int q = 0; q < 3; q++) {
            *(float2*)(oe + 2 * q) = make_float2(fe[2 * q], fe[2 * q + 1]);
            *(float2*)(oo + 2 * q) = make_float2(fo[2 * q], fo[2 * q + 1]);
        }
    }
}

extern "C" void kernel_launch(void* const* d_in, const int* in_sizes, int n_in,
                              void* d_out, int out_size)
{
    const int*   x     = (const int*)d_in[0];
    const float* h0    = (const float*)d_in[1];
    const float* emb   = (const float*)d_in[2];
    const float* Wcell = (const float*)d_in[3];
    const float* bcell = (const float*)d_in[4];
    const float* Wdec  = (const float*)d_in[5];
    const float* bdec  = (const float*)d_in[6];

    float* out = (float*)d_out;
    const long long outs_elems = (long long)BATCH * TLEN * VOCABN;
    float* hfin = nullptr;
    if ((long long)out_size >= outs_elems + (long long)BATCH * HID)
        hfin = out + outs_elems;

    cudaFuncSetAttribute(charrnn_cell_kernel,
                         cudaFuncAttributeMaxDynamicSharedMemorySize, C_SMEM_BYTES);
    cudaFuncSetAttribute(charrnn_dec_kernel,
                         cudaFuncAttributeMaxDynamicSharedMemorySize, D_SMEM_BYTES);

    charrnn_cell_kernel<<<NBLK, CTHR, C_SMEM_BYTES>>>(x, h0, emb, Wcell, bcell,
                                                      hfin);

    const int gblocks = (int)(((size_t)TLEN * BATCH) / D_ROWS);   // 8192
    charrnn_dec_kernel<<<gblocks, D_THR, D_SMEM_BYTES>>>(Wdec, bdec, out);
}

// round 11
// speedup vs baseline: 1.2034x; 1.2034x over previous
#include <cuda_runtime.h>

// CharRNN: B=512, T=2048, VOCAB=96, EMBED=32, HIDDEN=128
// R9: best measured combo.
//  Cell = R7 config (128 CTAs x 256 thr, thread = (j-quad, k-eighth),
//         per k: 2 LDS.64 + 8 FFMA2, 3-level reduce-scatter, 1 bar/step)
//         + hoisted xs/Et gathers (latency hidden under the FFMA loop).
//  Dec  = R8 config (8192 CTAs x 256 thr, 2 CTAs/SM, Mr=8 x Nr=6,
//         scalar W smem stride 97, H [k][rp] u64-packed smem).

#define VOCABN 96
#define EMBEDN 32
#define HID    128
#define BATCH  512
#define TLEN   2048
#define BROWS  4
#define NBLK   (BATCH / BROWS)   // 128
#define CTHR   256
#define WCS    (EMBEDN + HID)    // 160
#define ETS    132               // padded Et row stride (floats)

typedef unsigned long long u64;

// hidden states, row-pair packed: g_H[(t*256 + b/2)*128 + j] = (h[2rp][j], h[2rp+1][j])
__device__ u64 g_H[(size_t)TLEN * (BATCH / 2) * HID];

__device__ __forceinline__ u64 ffma2(u64 a, u64 b, u64 c) {
    u64 d;
    asm("fma.rn.f32x2 %0, %1, %2, %3;" : "=l"(d) : "l"(a), "l"(b), "l"(c));
    return d;
}
__device__ __forceinline__ u64 fadd2(u64 a, u64 b) {
    u64 d;
    asm("add.rn.f32x2 %0, %1, %2;" : "=l"(d) : "l"(a), "l"(b));
    return d;
}
__device__ __forceinline__ u64 pack2(float x, float y) {
    u64 d;
    asm("mov.b64 %0, {%1, %2};" : "=l"(d) : "f"(x), "f"(y));
    return d;
}
__device__ __forceinline__ float2 unpack2(u64 a) {
    float2 r;
    asm("mov.b64 {%0, %1}, %2;" : "=f"(r.x), "=f"(r.y) : "l"(a));
    return r;
}
__device__ __forceinline__ u64 shflx64(u64 v, int m) {
    float2 p = unpack2(v);
    p.x = __shfl_xor_sync(0xffffffffu, p.x, m);
    p.y = __shfl_xor_sync(0xffffffffu, p.y, m);
    return pack2(p.x, p.y);
}
__device__ __forceinline__ float tanh_fast(float x) {
    float e;
    asm("ex2.approx.f32 %0, %1;" : "=f"(e) : "f"(x * 2.8853900817779268f));
    float r;
    asm("rcp.approx.f32 %0, %1;" : "=f"(r) : "f"(e + 1.0f));
    return fmaf(-2.0f, r, 1.0f);
}

// ---------------- cell kernel ----------------
// smem: Et[96][132] floats, hp: 2 buf x 2 rp x 136 u64 (k -> k + (k>>4)),
//       xs: 2048*4 ints
#define HP_RP   136
#define HP_BUF  (2 * HP_RP)
#define F_ET 0
#define F_HP (F_ET + VOCABN*ETS)
#define F_XS (F_HP + 2*HP_BUF*2)
#define C_SMEM_FLOATS (F_XS + BROWS*TLEN)
#define C_SMEM_BYTES  (C_SMEM_FLOATS * 4)

__global__ void __launch_bounds__(CTHR, 1)
charrnn_cell_kernel(const int* __restrict__ x,
                    const float* __restrict__ h0,
                    const float* __restrict__ emb,
                    const float* __restrict__ Wcell,
                    const float* __restrict__ bcell,
                    float* __restrict__ hfin)
{
    extern __shared__ float smem[];
    float* Et  = smem + F_ET;
    u64*   hpU = (u64*)(smem + F_HP);
    int*   xs  = (int*)(smem + F_XS);

    const int tid = threadIdx.x;
    const int b0  = blockIdx.x * BROWS;

    const int s  = tid & 7;          // k-eighth (k in [16s, 16s+16))
    const int jq = tid >> 3;         // j-quad 0..31
    const int jb = jq * 4;

    // duplicated (w,w) weights: wd[jj][kk] for j = jb+jj, k = 16s+kk
    u64 wd[4][16];
    #pragma unroll
    for (int jj = 0; jj < 4; jj++) {
        const float* p = Wcell + (jb + jj) * WCS + EMBEDN + s * 16;
        #pragma unroll
        for (int kk = 0; kk < 16; kk++) {
            float w = p[kk];
            wd[jj][kk] = pack2(w, w);
        }
    }

    // Et table (threads 0..127)
    if (tid < HID) {
        const int j = tid;
        float we[EMBEDN];
        #pragma unroll
        for (int k = 0; k < EMBEDN; k++)
            we[k] = Wcell[j * WCS + k];
        const float bc = bcell[j];
        for (int vv = 0; vv < VOCABN; vv++) {
            float a = bc;
            #pragma unroll
            for (int k = 0; k < EMBEDN; k++)
                a = fmaf(emb[vv * EMBEDN + k], we[k], a);
            Et[vv * ETS + j] = a;
        }
    }

    // token prefetch: xs[t*4 + r] = x[(b0+r)*T + t]
    for (int i = tid; i < BROWS * TLEN; i += CTHR) {
        int t = i >> 2, r = i & 3;
        xs[i] = x[(b0 + r) * TLEN + t];
    }

    // initial h -> buffer 0 (row-pair packed, padded): tid = rp*128 + j
    {
        const int rp = tid >> 7;
        const int jj = tid & 127;
        u64 v = pack2(h0[(b0 + 2 * rp) * HID + jj],
                      h0[(b0 + 2 * rp + 1) * HID + jj]);
        hpU[rp * HP_RP + jj + (jj >> 4)] = v;
    }
    __syncthreads();

    const int rp   = s >> 2;               // my output row-pair
    const int jfin = jb + (s & 3);         // my output hidden index
    const int jfp  = jfin + (jfin >> 4);   // padded
    const size_t gbase = (size_t)(b0 >> 1) + rp;
    float th0 = 0.f, th1 = 0.f;

    #pragma unroll 1
    for (int t = 0; t < TLEN; t++) {
        // ---- hoisted gathers: issue early, consumed only in the tail ----
        const int i0 = xs[t * 4 + 2 * rp];
        const int i1 = xs[t * 4 + 2 * rp + 1];
        const float et0 = Et[i0 * ETS + jfin];
        const float et1 = Et[i1 * ETS + jfin];

        const u64* hb  = hpU + (t & 1) * HP_BUF;
        const u64* h0p = hb + 17 * s;          // rp 0, my k-slice (padded base)
        const u64* h1p = h0p + HP_RP;          // rp 1

        u64 a0[4] = {0, 0, 0, 0};
        u64 a1[4] = {0, 0, 0, 0};
        #pragma unroll
        for (int kk = 0; kk < 16; kk++) {
            u64 hA = h0p[kk];
            u64 hB = h1p[kk];
            #pragma unroll
            for (int jj = 0; jj < 4; jj++) {
                a0[jj] = ffma2(hA, wd[jj][kk], a0[jj]);
                a1[jj] = ffma2(hB, wd[jj][kk], a1[jj]);
            }
        }

        // reduce-scatter across 8 k-slices (xor 4, 2, 1)
        u64 kp4[4];
        #pragma unroll
        for (int jj = 0; jj < 4; jj++) {
            u64 keep = (s & 4) ? a1[jj] : a0[jj];
            u64 give = (s & 4) ? a0[jj] : a1[jj];
            kp4[jj] = fadd2(keep, shflx64(give, 4));
        }
        u64 kA = (s & 2) ? kp4[2] : kp4[0];
        u64 gA = (s & 2) ? kp4[0] : kp4[2];
        kA = fadd2(kA, shflx64(gA, 2));
        u64 kB = (s & 2) ? kp4[3] : kp4[1];
        u64 gB = (s & 2) ? kp4[1] : kp4[3];
        kB = fadd2(kB, shflx64(gB, 2));
        u64 kk2 = (s & 1) ? kB : kA;
        u64 gg  = (s & 1) ? kA : kB;
        kk2 = fadd2(kk2, shflx64(gg, 1));

        // finalize rows (2rp, 2rp+1) at hidden index jfin
        float2 u = unpack2(kk2);
        th0 = tanh_fast(u.x + et0);
        th1 = tanh_fast(u.y + et1);
        u64 hv = pack2(th0, th1);

        hpU[((t + 1) & 1) * HP_BUF + rp * HP_RP + jfp] = hv;
        g_H[((size_t)t * (BATCH / 2) + gbase) * HID + jfin] = hv;
        __syncthreads();
    }

    if (hfin) {
        hfin[(b0 + 2 * rp) * HID + jfin]     = th0;
        hfin[(b0 + 2 * rp + 1) * HID + jfin] = th1;
    }
}

// ---------------- decoder GEMM kernel (R8, unchanged) ----------------
// out[b][t][v] = H[t][b][:] . Wdec[v][:] + bdec[v]
// CTA: 128 rows (64 rp) x 96 v, 256 thr = 16 rg x 16 vg. Thread: Mr=8 x Nr=6.
#define D_ROWS 128
#define D_THR  256
#define WS_S   97

#define U_HTP  0
#define U_END  (U_HTP + 128*64)             // u64 units
#define D_WS_OFF   (U_END * 2)              // float index
#define D_BIAS_OFF (D_WS_OFF + 128*WS_S)
#define D_SMEM_FLOATS (D_BIAS_OFF + 96)
#define D_SMEM_BYTES  (D_SMEM_FLOATS * 4)

__global__ void __launch_bounds__(D_THR, 2)
charrnn_dec_kernel(const float* __restrict__ Wdec,   // [96][128]
                   const float* __restrict__ bdec,   // [96]
                   float* __restrict__ out)          // [512][2048][96]
{
    extern __shared__ u64 smemU[];
    u64*   htp  = smemU + U_HTP;                     // [k][rp]
    float* ws   = (float*)smemU + D_WS_OFF;          // [k][97]
    float* bias = (float*)smemU + D_BIAS_OFF;

    const int tid = threadIdx.x;
    const int t_idx = blockIdx.x >> 2;
    const int bb0   = (blockIdx.x & 3) * D_ROWS;
    const size_t rpg0 = (size_t)t_idx * (BATCH / 2) + (bb0 >> 1);

    // stage W scalar: ws[k*97 + v] = Wdec[v][k]
    for (int i = tid; i < VOCABN * HID; i += D_THR) {
        int v = i >> 7, k = i & 127;
        ws[k * WS_S + v] = Wdec[i];
    }
    if (tid < VOCABN) bias[tid] = bdec[tid];

    // stage H: htp[k][rp] = g_H[rpg0 + rp][k]
    {
        const int rp = tid >> 2;
        const int q  = tid & 3;
        const ulonglong2* src =
            (const ulonglong2*)(g_H + (rpg0 + rp) * HID + q * 32);
        #pragma unroll
        for (int i = 0; i < 16; i++) {
            ulonglong2 hv = src[i];
            int k = q * 32 + 2 * i;
            htp[(k + 0) * 64 + rp] = hv.x;
            htp[(k + 1) * 64 + rp] = hv.y;
        }
    }
    __syncthreads();

    const int vg = tid & 15;
    const int rg = tid >> 4;
    const int v0 = vg * 6;

    u64 acc[4][6];
    #pragma unroll
    for (int i = 0; i < 4; i++)
        #pragma unroll
        for (int q = 0; q < 6; q++)
            acc[i][q] = 0ull;

    const u64*   hB = htp + rg * 4;
    const float* wB = ws + v0;

    #pragma unroll 4
    for (int k = 0; k < HID; k++) {
        u64 h[4];
        {
            const ulonglong2* hp2 = (const ulonglong2*)(hB + k * 64);
            ulonglong2 hv0 = hp2[0];
            ulonglong2 hv1 = hp2[1];
            h[0] = hv0.x; h[1] = hv0.y; h[2] = hv1.x; h[3] = hv1.y;
        }
        #pragma unroll
        for (int q = 0; q < 6; q++) {
            float w = wB[k * WS_S + q];
            u64 w2 = pack2(w, w);
            #pragma unroll
            for (int i = 0; i < 4; i++)
                acc[i][q] = ffma2(h[i], w2, acc[i][q]);
        }
    }

    float bq[6];
    #pragma unroll
    for (int q = 0; q < 6; q++)
        bq[q] = bias[v0 + q];

    #pragma unroll
    for (int i = 0; i < 4; i++) {
        const int rpl = rg * 4 + i;
        const int be  = bb0 + 2 * rpl;
        float* oe = out + ((size_t)be * TLEN + t_idx) * VOCABN + v0;
        float* oo = oe + (size_t)TLEN * VOCABN;
        float fe[6], fo[6];
        #pragma unroll
        for (int q = 0; q < 6; q++) {
            float2 p = unpack2(acc[i][q]);
            fe[q] = p.x + bq[q];
            fo[q] = p.y + bq[q];
        }
        #pragma unroll
        for (int q = 0; q < 3; q++) {
            *(float2*)(oe + 2 * q) = make_float2(fe[2 * q], fe[2 * q + 1]);
            *(float2*)(oo + 2 * q) = make_float2(fo[2 * q], fo[2 * q + 1]);
        }
    }
}

extern "C" void kernel_launch(void* const* d_in, const int* in_sizes, int n_in,
                              void* d_out, int out_size)
{
    const int*   x     = (const int*)d_in[0];
    const float* h0    = (const float*)d_in[1];
    const float* emb   = (const float*)d_in[2];
    const float* Wcell = (const float*)d_in[3];
    const float* bcell = (const float*)d_in[4];
    const float* Wdec  = (const float*)d_in[5];
    const float* bdec  = (const float*)d_in[6];

    float* out = (float*)d_out;
    const long long outs_elems = (long long)BATCH * TLEN * VOCABN;
    float* hfin = nullptr;
    if ((long long)out_size >= outs_elems + (long long)BATCH * HID)
        hfin = out + outs_elems;

    cudaFuncSetAttribute(charrnn_cell_kernel,
                         cudaFuncAttributeMaxDynamicSharedMemorySize, C_SMEM_BYTES);
    cudaFuncSetAttribute(charrnn_dec_kernel,
                         cudaFuncAttributeMaxDynamicSharedMemorySize, D_SMEM_BYTES);

    charrnn_cell_kernel<<<NBLK, CTHR, C_SMEM_BYTES>>>(x, h0, emb, Wcell, bcell,
                                                      hfin);

    const int gblocks = (int)(((size_t)TLEN * BATCH) / D_ROWS);   // 8192
    charrnn_dec_kernel<<<gblocks, D_THR, D_SMEM_BYTES>>>(Wdec, bdec, out);
}